// round 17
// baseline (speedup 1.0000x reference)
#include <cuda_runtime.h>

#define NBLK 288   // 4 capsules per block -> 2 blocks per SM
#define NTHR 320   // 2 elements per thread

__global__ void __launch_bounds__(NTHR) mono_kernel(const float* __restrict__ x,
                                                    const float* __restrict__ W,
                                                    float* __restrict__ out) {
    const int t = threadIdx.x;            // 0..319
    const int blk = blockIdx.x;           // 0..287 -> capsules blk*4 .. blk*4+3

    __shared__ float4 sm4[256];           // stage-1 partials [bg*8 + i]
    __shared__ float4 sm4b[64];           // stage-2 partials [g*8 + i]
    __shared__ float sm_xs[32];           // xs[i*4 + clocal]
    __shared__ float sm_usq[40];          // per (clocal,u)
    __shared__ float sm_b[40];
    __shared__ float sm_e[40];
    __shared__ float sm_k[40];

    // ── W stream first: 2 elements/thread, 4 coalesced LDG.128 ──
    const size_t e0 = (size_t)blk * 640 + t;
    const size_t e1 = e0 + 320;
    const float4* w4 = reinterpret_cast<const float4*>(W);
    const float4 wA0 = __ldg(w4 + e0 * 2);
    const float4 wA1 = __ldg(w4 + e0 * 2 + 1);
    const float4 wB0 = __ldg(w4 + e1 * 2);
    const float4 wB1 = __ldg(w4 + e1 * 2 + 1);

    // ── x gather: this block's 4 capsules = ONE float4 column per (b,i) ──
    // x as float4 [b][i][q] with 288 q's; this block owns q = blk.
    // t<256: i = t&7, bg = t>>3 (32 groups of 8 batches); 8 loads, MLP=8.
    if (t < 256) {
        const int i = t & 7;
        const int bg = t >> 3;
        const float4* p = reinterpret_cast<const float4*>(x)
                        + (size_t)(bg * 8) * 2304 + i * 288 + blk;
        const float4 v0 = __ldg(p);
        const float4 v1 = __ldg(p + 2304);
        const float4 v2 = __ldg(p + 2 * 2304);
        const float4 v3 = __ldg(p + 3 * 2304);
        const float4 v4 = __ldg(p + 4 * 2304);
        const float4 v5 = __ldg(p + 5 * 2304);
        const float4 v6 = __ldg(p + 6 * 2304);
        const float4 v7 = __ldg(p + 7 * 2304);
        float4 a;
        a.x = ((v0.x + v1.x) + (v2.x + v3.x)) + ((v4.x + v5.x) + (v6.x + v7.x));
        a.y = ((v0.y + v1.y) + (v2.y + v3.y)) + ((v4.y + v5.y) + (v6.y + v7.y));
        a.z = ((v0.z + v1.z) + (v2.z + v3.z)) + ((v4.z + v5.z) + (v6.z + v7.z));
        a.w = ((v0.w + v1.w) + (v2.w + v3.w)) + ((v4.w + v5.w) + (v6.w + v7.w));
        sm4[t] = a;                       // [bg*8 + i]
    }
    __syncthreads();
    if (t < 64) {                         // 32 bg -> 8 groups
        const int i = t & 7;
        const int g = t >> 3;
        const float4 s0 = sm4[(g * 4 + 0) * 8 + i];
        const float4 s1 = sm4[(g * 4 + 1) * 8 + i];
        const float4 s2 = sm4[(g * 4 + 2) * 8 + i];
        const float4 s3 = sm4[(g * 4 + 3) * 8 + i];
        float4 a;
        a.x = (s0.x + s1.x) + (s2.x + s3.x);
        a.y = (s0.y + s1.y) + (s2.y + s3.y);
        a.z = (s0.z + s1.z) + (s2.z + s3.z);
        a.w = (s0.w + s1.w) + (s2.w + s3.w);
        sm4b[g * 8 + i] = a;
    }
    __syncthreads();
    if (t < 8) {                          // final 8-way sum -> scalar layout
        const int i = t;
        float4 a = sm4b[i];
        #pragma unroll
        for (int g = 1; g < 8; ++g) {
            const float4 s = sm4b[g * 8 + i];
            a.x += s.x; a.y += s.y; a.z += s.z; a.w += s.w;
        }
        sm_xs[i * 4 + 0] = a.x;
        sm_xs[i * 4 + 1] = a.y;
        sm_xs[i * 4 + 2] = a.z;
        sm_xs[i * 4 + 3] = a.w;
    }
    __syncthreads();

    // ── us for both elements; element A = cap lc0, element B = cap lc0+2 ──
    const int lc0 = t / 160;              // 0..1 (warp-aligned: 160 = 5 warps)
    const int r = t - lc0 * 160;          // u*16 + s
    const int u = r >> 4;
    const int ca = lc0;
    const int cb = lc0 + 2;

    const float usA = wA0.x * sm_xs[0 * 4 + ca] + wA0.y * sm_xs[1 * 4 + ca]
                    + wA0.z * sm_xs[2 * 4 + ca] + wA0.w * sm_xs[3 * 4 + ca]
                    + wA1.x * sm_xs[4 * 4 + ca] + wA1.y * sm_xs[5 * 4 + ca]
                    + wA1.z * sm_xs[6 * 4 + ca] + wA1.w * sm_xs[7 * 4 + ca];
    const float usB = wB0.x * sm_xs[0 * 4 + cb] + wB0.y * sm_xs[1 * 4 + cb]
                    + wB0.z * sm_xs[2 * 4 + cb] + wB0.w * sm_xs[3 * 4 + cb]
                    + wB1.x * sm_xs[4 * 4 + cb] + wB1.y * sm_xs[5 * 4 + cb]
                    + wB1.z * sm_xs[6 * 4 + cb] + wB1.w * sm_xs[7 * 4 + cb];

    // ||u_sum||^2 over the 16 s-lanes of each (c,u) group (16-aligned groups)
    float qA = usA * usA, qB = usB * usB;
    #pragma unroll
    for (int off = 8; off; off >>= 1) {
        qA += __shfl_xor_sync(0xffffffffu, qA, off);
        qB += __shfl_xor_sync(0xffffffffu, qB, off);
    }
    if ((t & 15) == 0) {
        sm_usq[ca * 10 + u] = qA;
        sm_usq[cb * 10 + u] = qB;
    }
    __syncthreads();

    // ── Scalar routing on t<40 (t = cc*10 + uu) ──
    {
        const bool act = (t < 40);
        const int cc = act ? (t / 10) : 0;
        const float usq = act ? sm_usq[t] : 0.f;
        float b = 0.f, cij = 0.1f, k = 0.f;   // softmax(0) = 1/10 exact

        #pragma unroll
        for (int it = 0; it < 3; ++it) {
            if (act) {
                const float msq = cij * cij * usq;
                const float coef = msq / (1.0f + msq) * rsqrtf(msq);
                k = coef * cij;
                if (it < 2) { b += k * usq * (1.0f / 256.0f); sm_b[t] = b; }
            }
            if (it < 2) {
                __syncthreads();
                float ex = 0.f;
                if (act) {
                    const float* bb = sm_b + cc * 10;
                    float m = bb[0];
                    #pragma unroll
                    for (int j = 1; j < 10; ++j) m = fmaxf(m, bb[j]);
                    ex = __expf(b - m);
                    sm_e[t] = ex;
                }
                __syncthreads();
                if (act) {
                    const float* ep = sm_e + cc * 10;
                    float d = ep[0];
                    #pragma unroll
                    for (int j = 1; j < 10; ++j) d += ep[j];
                    cij = ex / d;
                }
            }
        }
        if (act) sm_k[t] = k;
    }
    __syncthreads();

    // ── Final scale; coalesced stores ──
    out[e0] = sm_k[ca * 10 + u] * usA;
    out[e1] = sm_k[cb * 10 + u] * usB;
}

extern "C" void kernel_launch(void* const* d_in, const int* in_sizes, int n_in,
                              void* d_out, int out_size) {
    const float* x = (const float*)d_in[0];   // [256, 8, 1152]
    const float* W = (const float*)d_in[1];   // [1, 1152, 10, 16, 8]
    float* out = (float*)d_out;               // [1152, 10, 16]

    mono_kernel<<<NBLK, NTHR>>>(x, W, out);
}